// round 1
// baseline (speedup 1.0000x reference)
#include <cuda_runtime.h>

// 2-qubit dense gate on 24-qubit state, batch=4 (innermost).
// Flat float index = qindex * 4 + b.  qubit k -> bit (23-k) of qindex.
// support (5,12) -> bits 18 and 11.
//
// out[i] = sum_j G[i][j] * in[j],  i=2a+b (a=bit18 out, b=bit11 out),
//                                  j=2c+d (c=bit18 in,  d=bit11 in).
// Each thread: one rest-index (22 bits), 4x float4 load, 4x4 gate, 4x float4 store.

static constexpr unsigned REST_BITS = 22;          // 24 - 2 support qubits
static constexpr unsigned N_REST    = 1u << REST_BITS;
static constexpr unsigned BIT_C     = 1u << 18;    // qubit 5
static constexpr unsigned BIT_D     = 1u << 11;    // qubit 12

__global__ void __launch_bounds__(256)
quantum_gate2_kernel(const float4* __restrict__ in,
                     const float*  __restrict__ gate,
                     float4*       __restrict__ out)
{
    unsigned r = blockIdx.x * blockDim.x + threadIdx.x;
    // Expand rest index: insert zero bits at positions 11 and 18.
    unsigned low = r & 0x7FFu;           // bits 0..10
    unsigned mid = (r >> 11) & 0x3Fu;    // -> qindex bits 12..17
    unsigned hi  = r >> 17;              // -> qindex bits 19..23
    unsigned qb  = low | (mid << 12) | (hi << 19);

    // Load the 4 basis amplitudes (each a float4 across the batch).
    float4 v0 = in[qb];                  // c=0,d=0
    float4 v1 = in[qb | BIT_D];          // c=0,d=1
    float4 v2 = in[qb | BIT_C];          // c=1,d=0
    float4 v3 = in[qb | BIT_C | BIT_D];  // c=1,d=1

    // Gate: 16 floats, uniform broadcast load.
    float g[16];
#pragma unroll
    for (int i = 0; i < 16; i++) g[i] = __ldg(gate + i);

    float4 o[4];
#pragma unroll
    for (int i = 0; i < 4; i++) {
        o[i].x = g[4*i+0]*v0.x + g[4*i+1]*v1.x + g[4*i+2]*v2.x + g[4*i+3]*v3.x;
        o[i].y = g[4*i+0]*v0.y + g[4*i+1]*v1.y + g[4*i+2]*v2.y + g[4*i+3]*v3.y;
        o[i].z = g[4*i+0]*v0.z + g[4*i+1]*v1.z + g[4*i+2]*v2.z + g[4*i+3]*v3.z;
        o[i].w = g[4*i+0]*v0.w + g[4*i+1]*v1.w + g[4*i+2]*v2.w + g[4*i+3]*v3.w;
    }

    out[qb]                 = o[0];
    out[qb | BIT_D]         = o[1];
    out[qb | BIT_C]         = o[2];
    out[qb | BIT_C | BIT_D] = o[3];
}

extern "C" void kernel_launch(void* const* d_in, const int* in_sizes, int n_in,
                              void* d_out, int out_size)
{
    const float4* state = (const float4*)d_in[0];
    const float*  gate  = (const float*)d_in[1];
    float4*       out   = (float4*)d_out;

    const unsigned threads = 256;
    const unsigned blocks  = N_REST / threads;   // 2^22 / 256 = 16384
    quantum_gate2_kernel<<<blocks, threads>>>(state, gate, out);
}